// round 12
// baseline (speedup 1.0000x reference)
#include <cuda_runtime.h>
#include <cuda_bf16.h>
#include <math.h>
#include <stdint.h>

// ---------------- problem constants ----------------
#define GB   2
#define GS   2048
#define GD   4096
#define GH   32
#define GKH  8
#define GHD  128
#define QKV_OUT 6144
#define QKSTRIDE 5120     // q(4096) + k(1024) packed

// ---------------- device scratch ----------------
__device__ float g_qkv[GB*GS*QKV_OUT];                       // fp32 qkv (gemm out)
__device__ float2 g_cs[GS*64];                               // rope cos/sin table
__device__ __nv_bfloat16 g_xh[GB*GS*GD],      g_xl[GB*GS*GD];
__device__ __nv_bfloat16 g_wqkvh[QKV_OUT*GD], g_wqkvl[QKV_OUT*GD];
__device__ __nv_bfloat16 g_woh[GD*GD],        g_wol[GD*GD];
__device__ __nv_bfloat16 g_attnh[GB*GS*GD],   g_attnl[GB*GS*GD];
__device__ __nv_bfloat16 g_qkh[GB*GS*QKSTRIDE], g_qkl[GB*GS*QKSTRIDE];   // roped q(scaled)+k, bf16 hi/lo
__device__ __nv_bfloat16 g_vth[GB*GKH*GHD*GS],  g_vtl[GB*GKH*GHD*GS];    // V transposed [b,kh,d,s]

// ---------------- smem addr helper ----------------
__device__ __forceinline__ uint32_t smem_u32(const void* p){
    uint32_t a;
    asm("{ .reg .u64 t; cvta.to.shared.u64 t, %1; cvt.u32.u64 %0, t; }" : "=r"(a) : "l"(p));
    return a;
}

// ---------------- HMMA / cp.async helpers ----------------
__device__ __forceinline__ void ldmx4(uint32_t* r, uint32_t addr){
    asm volatile("ldmatrix.sync.aligned.m8n8.x4.shared.b16 {%0,%1,%2,%3}, [%4];"
        : "=r"(r[0]), "=r"(r[1]), "=r"(r[2]), "=r"(r[3]) : "r"(addr));
}
__device__ __forceinline__ void mma16816(float* c, const uint32_t* a, const uint32_t* b){
    asm volatile(
        "mma.sync.aligned.m16n8k16.row.col.f32.bf16.bf16.f32 "
        "{%0,%1,%2,%3}, {%4,%5,%6,%7}, {%8,%9}, {%0,%1,%2,%3};"
        : "+f"(c[0]), "+f"(c[1]), "+f"(c[2]), "+f"(c[3])
        : "r"(a[0]), "r"(a[1]), "r"(a[2]), "r"(a[3]), "r"(b[0]), "r"(b[1]));
}
__device__ __forceinline__ void cp16(uint32_t saddr, const void* g){
    asm volatile("cp.async.cg.shared.global [%0], [%1], 16;"
        :: "r"(saddr), "l"(__cvta_generic_to_global(g)) : "memory");
}
__device__ __forceinline__ void cp_commit(){
    asm volatile("cp.async.commit_group;" ::: "memory");
}
template <int N>
__device__ __forceinline__ void cp_wait(){
    asm volatile("cp.async.wait_group %0;" :: "n"(N) : "memory");
}

// ---------------- bf16 hi/lo helpers ----------------
__device__ __forceinline__ void hilo4(float4 v, unsigned long long& h, unsigned long long& l){
    __nv_bfloat16 h0 = __float2bfloat16(v.x);
    __nv_bfloat16 h1 = __float2bfloat16(v.y);
    __nv_bfloat16 h2 = __float2bfloat16(v.z);
    __nv_bfloat16 h3 = __float2bfloat16(v.w);
    __nv_bfloat16 l0 = __float2bfloat16(v.x - __bfloat162float(h0));
    __nv_bfloat16 l1 = __float2bfloat16(v.y - __bfloat162float(h1));
    __nv_bfloat16 l2 = __float2bfloat16(v.z - __bfloat162float(h2));
    __nv_bfloat16 l3 = __float2bfloat16(v.w - __bfloat162float(h3));
    h = (unsigned long long)__bfloat16_as_ushort(h0)
      | ((unsigned long long)__bfloat16_as_ushort(h1) << 16)
      | ((unsigned long long)__bfloat16_as_ushort(h2) << 32)
      | ((unsigned long long)__bfloat16_as_ushort(h3) << 48);
    l = (unsigned long long)__bfloat16_as_ushort(l0)
      | ((unsigned long long)__bfloat16_as_ushort(l1) << 16)
      | ((unsigned long long)__bfloat16_as_ushort(l2) << 32)
      | ((unsigned long long)__bfloat16_as_ushort(l3) << 48);
}
__device__ __forceinline__ void packhl(float f0, float f1, uint32_t& h, uint32_t& l){
    __nv_bfloat16 h0 = __float2bfloat16(f0);
    __nv_bfloat16 h1 = __float2bfloat16(f1);
    __nv_bfloat16 b0 = __float2bfloat16(f0 - __bfloat162float(h0));
    __nv_bfloat16 b1 = __float2bfloat16(f1 - __bfloat162float(h1));
    h = (uint32_t)__bfloat16_as_ushort(h0) | ((uint32_t)__bfloat16_as_ushort(h1) << 16);
    l = (uint32_t)__bfloat16_as_ushort(b0) | ((uint32_t)__bfloat16_as_ushort(b1) << 16);
}

// ---------------- fp32 -> bf16 hi/lo ----------------
__global__ __launch_bounds__(256) void cvt_pair_kernel(const float4* __restrict__ src,
                                                       unsigned long long* __restrict__ h,
                                                       unsigned long long* __restrict__ l,
                                                       int n4){
    const int i = blockIdx.x*blockDim.x + threadIdx.x;
    if (i < n4){
        unsigned long long hh, ll;
        hilo4(src[i], hh, ll);
        h[i] = hh;
        l[i] = ll;
    }
}

// ---------------- rope cos/sin table ----------------
__global__ __launch_bounds__(256) void cs_kernel(){
    const int idx = blockIdx.x*256 + threadIdx.x;   // GS*64
    const int pos = idx >> 6;
    const int i   = idx & 63;
    const float inv = powf(500000.0f, -(float)i * (1.0f/64.0f));
    float sn, cs;
    sincosf((float)pos * inv, &sn, &cs);
    g_cs[idx] = make_float2(cs, sn);
}

// ---------------- fused RoPE + bf16 hi/lo q/k conversion ----------------
// reads fp32 g_qkv, writes g_qkh/g_qkl (stride 5120). scale folded into q.
__global__ __launch_bounds__(256) void rope_fused_kernel(){
    const int row = blockIdx.x;                  // b*S + s
    const int pos = row & (GS-1);
    const float SCL = 0.08838834764831845f;
    const float* src = g_qkv + (size_t)row * QKV_OUT;
    __nv_bfloat16* dh = g_qkh + (size_t)row * QKSTRIDE;
    __nv_bfloat16* dl = g_qkl + (size_t)row * QKSTRIDE;

    for (int it = threadIdx.x; it < 40*16; it += 256){
        const int hh = it >> 4;
        const int qi = (it & 15) * 4;
        const int off = (hh < GH) ? hh*GHD : GH*GHD + (hh-GH)*GHD;
        const float4 x1 = *(const float4*)(src + off + qi);
        const float4 x2 = *(const float4*)(src + off + qi + 64);
        const float2 c0 = g_cs[pos*64 + qi];
        const float2 c1 = g_cs[pos*64 + qi + 1];
        const float2 c2 = g_cs[pos*64 + qi + 2];
        const float2 c3 = g_cs[pos*64 + qi + 3];
        float4 r1 = make_float4(x1.x*c0.x - x2.x*c0.y, x1.y*c1.x - x2.y*c1.y,
                                x1.z*c2.x - x2.z*c2.y, x1.w*c3.x - x2.w*c3.y);
        float4 r2 = make_float4(x2.x*c0.x + x1.x*c0.y, x2.y*c1.x + x1.y*c1.y,
                                x2.z*c2.x + x1.z*c2.y, x2.w*c3.x + x1.w*c3.y);
        if (hh < GH){
            r1.x*=SCL; r1.y*=SCL; r1.z*=SCL; r1.w*=SCL;
            r2.x*=SCL; r2.y*=SCL; r2.z*=SCL; r2.w*=SCL;
        }
        unsigned long long h1, l1, h2, l2;
        hilo4(r1, h1, l1);
        hilo4(r2, h2, l2);
        *(unsigned long long*)(dh + off + qi)      = h1;
        *(unsigned long long*)(dl + off + qi)      = l1;
        *(unsigned long long*)(dh + off + qi + 64) = h2;
        *(unsigned long long*)(dl + off + qi + 64) = l2;
    }
}

// ---------------- V transpose conversion: [b,s,kh,d] -> [b,kh,d,s] bf16 hi/lo ----------------
__global__ void vconv_kernel(){
    __shared__ float t[32][33];
    const int s0 = blockIdx.x*32;
    const int d0 = blockIdx.y*32;
    const int bkh = blockIdx.z;
    const int b  = bkh >> 3, kh = bkh & 7;
    #pragma unroll
    for (int i = 0; i < 4; ++i){
        const int s = s0 + threadIdx.y + i*8;
        const int d = d0 + threadIdx.x;
        t[threadIdx.y + i*8][threadIdx.x] =
            g_qkv[(size_t)(b*GS + s)*QKV_OUT + QKSTRIDE + kh*GHD + d];
    }
    __syncthreads();
    #pragma unroll
    for (int i = 0; i < 4; ++i){
        const int d = d0 + threadIdx.y + i*8;
        const int s = s0 + threadIdx.x;
        const float v = t[threadIdx.x][threadIdx.y + i*8];
        const __nv_bfloat16 h = __float2bfloat16(v);
        const __nv_bfloat16 l = __float2bfloat16(v - __bfloat162float(h));
        const size_t o = ((size_t)(bkh*GHD + d))*GS + s;
        g_vth[o] = h;
        g_vtl[o] = l;
    }
}

// ---------------- HMMA bf16x3 GEMM: 128x256 tile, 3-stage cp.async ----------------
#define GP    80
#define TBA   10240          // 128*80
#define TBB   20480          // 256*80
#define STG   (2*TBA + 2*TBB)     // 61440
#define NST   3
#define GEMM_SMEM (NST*STG)       // 184320

__device__ __forceinline__ void gemm_bf16x3_body(
    const __nv_bfloat16* __restrict__ Ah, const __nv_bfloat16* __restrict__ Al,
    const __nv_bfloat16* __restrict__ Bh, const __nv_bfloat16* __restrict__ Bl,
    float* __restrict__ C, int N, int K)
{
    extern __shared__ __align__(16) char dyn[];
    const uint32_t sb = smem_u32(dyn);

    const int tid  = threadIdx.x;
    const int wid  = tid >> 5;
    const int lane = tid & 31;
    const int wm   = (wid & 1) * 64;
    const int wn   = (wid >> 1) * 64;
    const int m0   = blockIdx.y * 128;
    const int n0   = blockIdx.x * 256;

    const __nv_bfloat16* Ahb = Ah + (size_t)m0*K;
    const __nv_bfloat16* Alb = Al + (size_t)m0*K;
    const __nv_bfloat16* Bhb = Bh + (size_t)n0*K;
    const __nv_bfloat16* Blb = Bl + (size_t)n0*K;

    auto issue = [&](int s, int k0){
        const uint32_t stg = sb + (uint32_t)(s*STG);
        // A tiles: 512 cp16 each (hi, lo)
        #pragma unroll
        for (int p = 0; p < 2; ++p){
            const int idx = p*256 + tid;
            const int row = idx >> 2;
            const int c16 = idx & 3;
            cp16(stg + (uint32_t)(row*GP + c16*16),       Ahb + (size_t)row*K + k0 + c16*8);
            cp16(stg + (uint32_t)(TBA + row*GP + c16*16), Alb + (size_t)row*K + k0 + c16*8);
        }
        // B tiles: 1024 cp16 each
        #pragma unroll
        for (int p = 0; p < 4; ++p){
            const int idx = p*256 + tid;
            const int row = idx >> 2;
            const int c16 = idx & 3;
            cp16(stg + (uint32_t)(2*TBA + row*GP + c16*16),       Bhb + (size_t)row*K + k0 + c16*8);
            cp16(stg + (uint32_t)(2*TBA + TBB + row*GP + c16*16), Blb + (size_t)row*K + k0 + c16*8);
        }
        cp_commit();
    };

    float acc[4][8][4];
    #pragma unroll
    for (int i=0;i<4;i++)
        #pragma unroll
        for (int j=0;j<8;j++)
            #pragma unroll
            for (int c=0;c<4;c++) acc[i][j][c] = 0.f;

    const int NIT = K / 32;
    issue(0, 0);
    issue(1, 32);

    const int arow = wm + (lane & 15);
    const int akb  = (lane >> 4) * 16;
    const int brow = wn + (lane & 7) + ((lane >> 4) << 3);
    const int bkb  = ((lane >> 3) & 1) * 16;

    for (int it = 0; it < NIT; ++it){
        if (it + 1 < NIT) cp_wait<1>(); else cp_wait<0>();
        __syncthreads();
        if (it + 2 < NIT) issue((it+2) % NST, (it+2)*32);

        const uint32_t stage = sb + (uint32_t)((it % NST) * STG);
        #pragma unroll
        for (int ks = 0; ks < 2; ++ks){
            uint32_t ah[4][4], al[4][4], bh[4][4], bl[4][4];
            #pragma unroll
            for (int mi = 0; mi < 4; ++mi){
                const uint32_t ad = stage + (uint32_t)((arow + mi*16)*GP + ks*32 + akb);
                ldmx4(ah[mi], ad);
                ldmx4(al[mi], ad + TBA);
            }
            #pragma unroll
            for (int n4 = 0; n4 < 4; ++n4){
                const uint32_t bd = stage + (uint32_t)(2*TBA + (brow + n4*16)*GP + ks*32 + bkb);
                ldmx4(bh[n4], bd);
                ldmx4(bl[n4], bd + TBB);
            }
            #pragma unroll
            for (int mi = 0; mi < 4; ++mi)
                #pragma unroll
                for (int ni = 0; ni < 8; ++ni){
                    const uint32_t* bhp = &bh[ni>>1][(ni&1)*2];
                    const uint32_t* blp = &bl[ni>>1][(ni&1)*2];
                    mma16816(acc[mi][ni], ah[mi], bhp);
                    mma16816(acc[mi][ni], ah[mi], blp);
                    mma16816(acc[mi][ni], al[mi], bhp);
                }
        }
        __syncthreads();
    }

    const int erow = (lane >> 2);
    const int ecol = (lane & 3) * 2;
    #pragma unroll
    for (int mi = 0; mi < 4; ++mi){
        #pragma unroll
        for (int ni = 0; ni < 8; ++ni){
            const int gm = m0 + wm + mi*16 + erow;
            const int gn = n0 + wn + ni*8 + ecol;
            *(float2*)(C + (size_t)gm*N + gn)     = make_float2(acc[mi][ni][0], acc[mi][ni][1]);
            *(float2*)(C + (size_t)(gm+8)*N + gn) = make_float2(acc[mi][ni][2], acc[mi][ni][3]);
        }
    }
}

__global__ __launch_bounds__(256, 1) void gemm_qkv_kernel(){
    gemm_bf16x3_body(g_xh, g_xl, g_wqkvh, g_wqkvl, g_qkv, QKV_OUT, GD);
}
__global__ __launch_bounds__(256, 1) void gemm_out_kernel(float* __restrict__ out){
    gemm_bf16x3_body(g_attnh, g_attnl, g_woh, g_wol, out, GD, GD);
}

// ---------------- HMMA flash attention (bf16x3, causal, GQA 4:1) ----------------
#define PQ 272
#define PK 272
#define PV 144
#define SQ_BYTES (128*PQ)
#define SK_BYTES (64*PK)
#define SV_BYTES (128*PV)
#define KV_STAGE (2*SK_BYTES + 2*SV_BYTES)
#define ATT_SMEM (2*SQ_BYTES + 2*KV_STAGE)

__global__ __launch_bounds__(256, 1) void attn_mma_kernel(){
    extern __shared__ __align__(16) char smraw[];
    const uint32_t sb = smem_u32(smraw);
    const int tid  = threadIdx.x;
    const int w    = tid >> 5;
    const int lane = tid & 31;
    const int qt = blockIdx.x, h = blockIdx.y, b = blockIdx.z;
    const int kh = h >> 2;

    const __nv_bfloat16* qhB = g_qkh + (size_t)(b*GS)*QKSTRIDE + h*GHD;
    const __nv_bfloat16* qlB = g_qkl + (size_t)(b*GS)*QKSTRIDE + h*GHD;
    const __nv_bfloat16* khB = g_qkh + (size_t)(b*GS)*QKSTRIDE + GD + kh*GHD;
    const __nv_bfloat16* klB = g_qkl + (size_t)(b*GS)*QKSTRIDE + GD + kh*GHD;
    const __nv_bfloat16* vhB = g_vth + (size_t)((b*GKH + kh)*GHD)*GS;
    const __nv_bfloat16* vlB = g_vtl + (size_t)((b*GKH + kh)*GHD)*GS;

    #pragma unroll
    for (int p = 0; p < 16; ++p){
        const int idx  = p*256 + tid;
        const int part = idx >> 11;
        const int rem  = idx & 2047;
        const int row  = rem >> 4;
        const int ch   = rem & 15;
        const __nv_bfloat16* src = (part ? qlB : qhB) + (size_t)(qt*128 + row)*QKSTRIDE + ch*8;
        cp16(sb + (uint32_t)(part*SQ_BYTES + row*PQ + ch*16), src);
    }
    cp_commit();

    auto issue_kv = [&](int kt){
        const uint32_t stg = sb + 2*SQ_BYTES + (uint32_t)((kt & 1) * KV_STAGE);
        #pragma unroll
        for (int p = 0; p < 16; ++p){
            const int idx = p*256 + tid;
            if (idx < 2048){
                const int part = idx >> 10;
                const int rem  = idx & 1023;
                const int row  = rem >> 4;
                const int ch   = rem & 15;
                const __nv_bfloat16* src = (part ? klB : khB) + (size_t)(kt*64 + row)*QKSTRIDE + ch*8;
                cp16(stg + (uint32_t)(part*SK_BYTES + row*PK + ch*16), src);
            } else {
                const int j    = idx - 2048;
                const int part = j >> 10;
                const int rem  = j & 1023;
                const int row  = rem >> 3;
                const int ch   = rem & 7;
                const __nv_bfloat16* src = (part ? vlB : vhB) + (size_t)row*GS + kt*64 + ch*8;
                cp16(stg + (uint32_t)(2*SK_BYTES + part*SV_BYTES + row*PV + ch*16), src);
            }
        }
        cp_commit();
    };

    issue_kv(0);

    const int arow = w*16 + (lane & 15);
    const int akb  = (lane >> 4) * 16;
    const int brow = (lane & 7) + ((lane >> 4) << 3);
    const int bkb  = ((lane >> 3) & 1) * 16;

    float oacc[16][4];
    #pragma unroll
    for (int i = 0; i < 16; ++i)
        #pragma unroll
        for (int c = 0; c < 4; ++c) oacc[i][c] = 0.f;
    float mr0 = -1e30f, mr1 = -1e30f, lr0 = 0.f, lr1 = 0.f;

    const int mx = 2*qt + 1;
    for (int kt = 0; kt <= mx; ++kt){
        cp_wait<0>();
        __syncthreads();
        if (kt < mx) issue_kv(kt+1);
        const uint32_t stg = sb + 2*SQ_BYTES + (uint32_t)((kt & 1) * KV_STAGE);

        float sacc[8][4];
        #pragma unroll
        for (int nf = 0; nf < 8; ++nf)
            #pragma unroll
            for (int c = 0; c < 4; ++c) sacc[nf][c] = 0.f;

        #pragma unroll
        for (int ks = 0; ks < 8; ++ks){
            uint32_t qh_t[4], ql_t[4];
            const uint32_t qa = sb + (uint32_t)(arow*PQ + ks*32 + akb);
            ldmx4(qh_t, qa);
            ldmx4(ql_t, qa + SQ_BYTES);
            uint32_t kfh[4][4], kfl[4][4];
            #pragma unroll
            for (int n4 = 0; n4 < 4; ++n4){
                const uint32_t ka = stg + (uint32_t)((brow + n4*16)*PK + ks*32 + bkb);
                ldmx4(kfh[n4], ka);
                ldmx4(kfl[n4], ka + SK_BYTES);
            }
            #pragma unroll
            for (int nf = 0; nf < 8; ++nf){
                const uint32_t* bh = &kfh[nf>>1][(nf&1)*2];
                const uint32_t* bl = &kfl[nf>>1][(nf&1)*2];
                mma16816(sacc[nf], qh_t, bh);
                mma16816(sacc[nf], qh_t, bl);
                mma16816(sacc[nf], ql_t, bh);
            }
        }

        if (kt >= 2*qt){
            const int r0 = qt*128 + w*16 + (lane >> 2);
            const int cb = kt*64 + (lane & 3)*2;
            #pragma unroll
            for (int nf = 0; nf < 8; ++nf){
                const int c = cb + nf*8;
                if (c     > r0)     sacc[nf][0] = -1e30f;
                if (c + 1 > r0)     sacc[nf][1] = -1e30f;
                if (c     > r0 + 8) sacc[nf][2] = -1e30f;
                if (c + 1 > r0 + 8) sacc[nf][3] = -1e30f;
            }
        }

        float rm0 = -1e30f, rm1 = -1e30f;
        #pragma unroll
        for (int nf = 0; nf < 8; ++nf){
            rm0 = fmaxf(rm0, fmaxf(sacc[nf][0], sacc[nf][1]));
            rm1 = fmaxf(rm1, fmaxf(sacc[nf][2], sacc[nf][3]));
        }
        rm0 = fmaxf(rm0, __shfl_xor_sync(0xffffffffu, rm0, 1));
        rm0 = fmaxf(rm0, __shfl_xor_sync(0xffffffffu, rm0, 2));
        rm1 = fmaxf(rm1, __shfl_xor_sync(0xffffffffu, rm1, 1));
        rm1 = fmaxf(rm1, __shfl_xor_sync(0xffffffffu, rm1, 2));
        const float mn0 = fmaxf(mr0, rm0);
        const float mn1 = fmaxf(mr1, rm1);
        const float a0 = __expf(mr0 - mn0);
        const float a1 = __expf(mr1 - mn1);
        float ps0 = 0.f, ps1 = 0.f;
        #pragma unroll
        for (int nf = 0; nf < 8; ++nf){
            sacc[nf][0] = __expf(sacc[nf][0] - mn0); ps0 += sacc[nf][0];
            sacc[nf][1] = __expf(sacc[nf][1] - mn0); ps0 += sacc[nf][1];
            sacc[nf][2] = __expf(sacc[nf][2] - mn1); ps1 += sacc[nf][2];
            sacc[nf][3] = __expf(sacc[nf][3] - mn1); ps1 += sacc[nf][3];
        }
        ps0 += __shfl_xor_sync(0xffffffffu, ps0, 1);
        ps0 += __shfl_xor_sync(0xffffffffu, ps0, 2);
        ps1 += __shfl_xor_sync(0xffffffffu, ps1, 1);
        ps1 += __shfl_xor_sync(0xffffffffu, ps1, 2);
        lr0 = lr0*a0 + ps0;  mr0 = mn0;
        lr1 = lr1*a1 + ps1;  mr1 = mn1;
        #pragma unroll
        for (int nf = 0; nf < 16; ++nf){
            oacc[nf][0] *= a0; oacc[nf][1] *= a0;
            oacc[nf][2] *= a1; oacc[nf][3] *= a1;
        }

        #pragma unroll
        for (int ks = 0; ks < 4; ++ks){
            uint32_t pah[4], pal[4];
            packhl(sacc[2*ks][0],   sacc[2*ks][1],   pah[0], pal[0]);
            packhl(sacc[2*ks][2],   sacc[2*ks][3],   pah[1], pal[1]);
            packhl(sacc[2*ks+1][0], sacc[2*ks+1][1], pah[2], pal[2]);
            packhl(sacc[2*ks+1][2], sacc[2*ks+1][3], pah[3], pal[3]);
            #pragma unroll
            for (int nd2 = 0; nd2 < 8; ++nd2){
                uint32_t vfh[4], vfl[4];
                const uint32_t va = stg + (uint32_t)(2*SK_BYTES + (brow + nd2*16)*PV + ks*32 + bkb);
                ldmx4(vfh, va);
                ldmx4(vfl, va + SV_BYTES);
                mma16816(oacc[nd2*2],   pah, &vfh[0]);
                mma16816(oacc[nd2*2],   pah, &vfl[0]);
                mma16816(oacc[nd2*2],   pal, &vfh[0]);
                mma16816(oacc[nd2*2+1], pah, &vfh[2]);
                mma16816(oacc[nd2*2+1], pah, &vfl[2]);
                mma16816(oacc[nd2*2+1], pal, &vfh[2]);
            }
        }
    }

    const float i0 = 1.f / lr0;
    const float i1 = 1.f / lr1;
    const int gr0 = b*GS + qt*128 + w*16 + (lane >> 2);
    const int cb  = h*GHD + (lane & 3)*2;
    #pragma unroll
    for (int nf = 0; nf < 16; ++nf){
        const float v0 = oacc[nf][0]*i0, v1 = oacc[nf][1]*i0;
        const float v2 = oacc[nf][2]*i1, v3 = oacc[nf][3]*i1;
        uint32_t h01, l01, h23, l23;
        packhl(v0, v1, h01, l01);
        packhl(v2, v3, h23, l23);
        const size_t o0 = (size_t)gr0*GD + cb + nf*8;
        const size_t o1 = (size_t)(gr0+8)*GD + cb + nf*8;
        *(uint32_t*)(g_attnh + o0) = h01;
        *(uint32_t*)(g_attnl + o0) = l01;
        *(uint32_t*)(g_attnh + o1) = h23;
        *(uint32_t*)(g_attnl + o1) = l23;
    }
}

// ---------------- launch ----------------
extern "C" void kernel_launch(void* const* d_in, const int* in_sizes, int n_in,
                              void* d_out, int out_size)
{
    const float* x    = (const float*)d_in[0];
    const float* Wqkv = (const float*)d_in[1];
    const float* Wo   = (const float*)d_in[2];
    float* out = (float*)d_out;

    cudaFuncSetAttribute(gemm_qkv_kernel, cudaFuncAttributeMaxDynamicSharedMemorySize, GEMM_SMEM);
    cudaFuncSetAttribute(gemm_out_kernel, cudaFuncAttributeMaxDynamicSharedMemorySize, GEMM_SMEM);
    cudaFuncSetAttribute(attn_mma_kernel, cudaFuncAttributeMaxDynamicSharedMemorySize, ATT_SMEM);

    unsigned long long *xh, *xl, *wqh, *wql, *woh, *wol;
    cudaGetSymbolAddress((void**)&xh,  g_xh);
    cudaGetSymbolAddress((void**)&xl,  g_xl);
    cudaGetSymbolAddress((void**)&wqh, g_wqkvh);
    cudaGetSymbolAddress((void**)&wql, g_wqkvl);
    cudaGetSymbolAddress((void**)&woh, g_woh);
    cudaGetSymbolAddress((void**)&wol, g_wol);

    const int nx  = GB*GS*GD/4;
    const int nwq = QKV_OUT*GD/4;
    const int nwo = GD*GD/4;
    cvt_pair_kernel<<<(nx +255)/256, 256>>>((const float4*)x,    xh,  xl,  nx);
    cvt_pair_kernel<<<(nwq+255)/256, 256>>>((const float4*)Wqkv, wqh, wql, nwq);
    cvt_pair_kernel<<<(nwo+255)/256, 256>>>((const float4*)Wo,   woh, wol, nwo);
    cs_kernel<<<(GS*64)/256, 256>>>();

    dim3 g1(QKV_OUT/256, (GB*GS)/128);
    gemm_qkv_kernel<<<g1, 256, GEMM_SMEM>>>();

    rope_fused_kernel<<<GB*GS, 256>>>();

    dim3 gv(GS/32, GHD/32, GB*GKH);
    vconv_kernel<<<gv, dim3(32,8)>>>();

    dim3 ga(GS/128, GH, GB);
    attn_mma_kernel<<<ga, 256, ATT_SMEM>>>();

    dim3 g2(GD/256, (GB*GS)/128);
    gemm_out_kernel<<<g2, 256, GEMM_SMEM>>>(out);
}

// round 13
// speedup vs baseline: 1.0001x; 1.0001x over previous
#include <cuda_runtime.h>
#include <cuda_bf16.h>
#include <math.h>
#include <stdint.h>

// ---------------- problem constants ----------------
#define GB   2
#define GS   2048
#define GD   4096
#define GH   32
#define GKH  8
#define GHD  128
#define QKV_OUT 6144
#define QKSTRIDE 5120     // q(4096) + k(1024) packed

// ---------------- device scratch ----------------
__device__ float g_qkv[GB*GS*QKV_OUT];                       // fp32 qkv (gemm out)
__device__ float2 g_cs[GS*64];                               // rope cos/sin table
__device__ __nv_bfloat16 g_xh[GB*GS*GD],      g_xl[GB*GS*GD];
__device__ __nv_bfloat16 g_wqkvh[QKV_OUT*GD], g_wqkvl[QKV_OUT*GD];
__device__ __nv_bfloat16 g_woh[GD*GD],        g_wol[GD*GD];
__device__ __nv_bfloat16 g_attnh[GB*GS*GD],   g_attnl[GB*GS*GD];
__device__ __nv_bfloat16 g_qkh[GB*GS*QKSTRIDE], g_qkl[GB*GS*QKSTRIDE];   // roped q(scaled)+k, bf16 hi/lo
__device__ __nv_bfloat16 g_vth[GB*GKH*GHD*GS],  g_vtl[GB*GKH*GHD*GS];    // V transposed [b,kh,d,s]

// ---------------- smem addr helper ----------------
__device__ __forceinline__ uint32_t smem_u32(const void* p){
    uint32_t a;
    asm("{ .reg .u64 t; cvta.to.shared.u64 t, %1; cvt.u32.u64 %0, t; }" : "=r"(a) : "l"(p));
    return a;
}

// ---------------- HMMA / cp.async helpers ----------------
__device__ __forceinline__ void ldmx4(uint32_t* r, uint32_t addr){
    asm volatile("ldmatrix.sync.aligned.m8n8.x4.shared.b16 {%0,%1,%2,%3}, [%4];"
        : "=r"(r[0]), "=r"(r[1]), "=r"(r[2]), "=r"(r[3]) : "r"(addr));
}
__device__ __forceinline__ void mma16816(float* c, const uint32_t* a, const uint32_t* b){
    asm volatile(
        "mma.sync.aligned.m16n8k16.row.col.f32.bf16.bf16.f32 "
        "{%0,%1,%2,%3}, {%4,%5,%6,%7}, {%8,%9}, {%0,%1,%2,%3};"
        : "+f"(c[0]), "+f"(c[1]), "+f"(c[2]), "+f"(c[3])
        : "r"(a[0]), "r"(a[1]), "r"(a[2]), "r"(a[3]), "r"(b[0]), "r"(b[1]));
}
__device__ __forceinline__ void cp16(uint32_t saddr, const void* g){
    asm volatile("cp.async.cg.shared.global [%0], [%1], 16;"
        :: "r"(saddr), "l"(__cvta_generic_to_global(g)) : "memory");
}
__device__ __forceinline__ void cp_commit(){
    asm volatile("cp.async.commit_group;" ::: "memory");
}
template <int N>
__device__ __forceinline__ void cp_wait(){
    asm volatile("cp.async.wait_group %0;" :: "n"(N) : "memory");
}

// ---------------- bf16 hi/lo helpers ----------------
__device__ __forceinline__ void hilo4(float4 v, unsigned long long& h, unsigned long long& l){
    __nv_bfloat16 h0 = __float2bfloat16(v.x);
    __nv_bfloat16 h1 = __float2bfloat16(v.y);
    __nv_bfloat16 h2 = __float2bfloat16(v.z);
    __nv_bfloat16 h3 = __float2bfloat16(v.w);
    __nv_bfloat16 l0 = __float2bfloat16(v.x - __bfloat162float(h0));
    __nv_bfloat16 l1 = __float2bfloat16(v.y - __bfloat162float(h1));
    __nv_bfloat16 l2 = __float2bfloat16(v.z - __bfloat162float(h2));
    __nv_bfloat16 l3 = __float2bfloat16(v.w - __bfloat162float(h3));
    h = (unsigned long long)__bfloat16_as_ushort(h0)
      | ((unsigned long long)__bfloat16_as_ushort(h1) << 16)
      | ((unsigned long long)__bfloat16_as_ushort(h2) << 32)
      | ((unsigned long long)__bfloat16_as_ushort(h3) << 48);
    l = (unsigned long long)__bfloat16_as_ushort(l0)
      | ((unsigned long long)__bfloat16_as_ushort(l1) << 16)
      | ((unsigned long long)__bfloat16_as_ushort(l2) << 32)
      | ((unsigned long long)__bfloat16_as_ushort(l3) << 48);
}
__device__ __forceinline__ void packhl(float f0, float f1, uint32_t& h, uint32_t& l){
    __nv_bfloat16 h0 = __float2bfloat16(f0);
    __nv_bfloat16 h1 = __float2bfloat16(f1);
    __nv_bfloat16 b0 = __float2bfloat16(f0 - __bfloat162float(h0));
    __nv_bfloat16 b1 = __float2bfloat16(f1 - __bfloat162float(h1));
    h = (uint32_t)__bfloat16_as_ushort(h0) | ((uint32_t)__bfloat16_as_ushort(h1) << 16);
    l = (uint32_t)__bfloat16_as_ushort(b0) | ((uint32_t)__bfloat16_as_ushort(b1) << 16);
}

// ---------------- fp32 -> bf16 hi/lo ----------------
__global__ __launch_bounds__(256) void cvt_pair_kernel(const float4* __restrict__ src,
                                                       unsigned long long* __restrict__ h,
                                                       unsigned long long* __restrict__ l,
                                                       int n4){
    const int i = blockIdx.x*blockDim.x + threadIdx.x;
    if (i < n4){
        unsigned long long hh, ll;
        hilo4(src[i], hh, ll);
        h[i] = hh;
        l[i] = ll;
    }
}

// ---------------- rope cos/sin table ----------------
__global__ __launch_bounds__(256) void cs_kernel(){
    const int idx = blockIdx.x*256 + threadIdx.x;   // GS*64
    const int pos = idx >> 6;
    const int i   = idx & 63;
    const float inv = powf(500000.0f, -(float)i * (1.0f/64.0f));
    float sn, cs;
    sincosf((float)pos * inv, &sn, &cs);
    g_cs[idx] = make_float2(cs, sn);
}

// ---------------- fused RoPE + bf16 hi/lo q/k conversion ----------------
// reads fp32 g_qkv, writes g_qkh/g_qkl (stride 5120). scale folded into q.
__global__ __launch_bounds__(256) void rope_fused_kernel(){
    const int row = blockIdx.x;                  // b*S + s
    const int pos = row & (GS-1);
    const float SCL = 0.08838834764831845f;
    const float* src = g_qkv + (size_t)row * QKV_OUT;
    __nv_bfloat16* dh = g_qkh + (size_t)row * QKSTRIDE;
    __nv_bfloat16* dl = g_qkl + (size_t)row * QKSTRIDE;

    for (int it = threadIdx.x; it < 40*16; it += 256){
        const int hh = it >> 4;
        const int qi = (it & 15) * 4;
        const int off = (hh < GH) ? hh*GHD : GH*GHD + (hh-GH)*GHD;
        const float4 x1 = *(const float4*)(src + off + qi);
        const float4 x2 = *(const float4*)(src + off + qi + 64);
        const float2 c0 = g_cs[pos*64 + qi];
        const float2 c1 = g_cs[pos*64 + qi + 1];
        const float2 c2 = g_cs[pos*64 + qi + 2];
        const float2 c3 = g_cs[pos*64 + qi + 3];
        float4 r1 = make_float4(x1.x*c0.x - x2.x*c0.y, x1.y*c1.x - x2.y*c1.y,
                                x1.z*c2.x - x2.z*c2.y, x1.w*c3.x - x2.w*c3.y);
        float4 r2 = make_float4(x2.x*c0.x + x1.x*c0.y, x2.y*c1.x + x1.y*c1.y,
                                x2.z*c2.x + x1.z*c2.y, x2.w*c3.x + x1.w*c3.y);
        if (hh < GH){
            r1.x*=SCL; r1.y*=SCL; r1.z*=SCL; r1.w*=SCL;
            r2.x*=SCL; r2.y*=SCL; r2.z*=SCL; r2.w*=SCL;
        }
        unsigned long long h1, l1, h2, l2;
        hilo4(r1, h1, l1);
        hilo4(r2, h2, l2);
        *(unsigned long long*)(dh + off + qi)      = h1;
        *(unsigned long long*)(dl + off + qi)      = l1;
        *(unsigned long long*)(dh + off + qi + 64) = h2;
        *(unsigned long long*)(dl + off + qi + 64) = l2;
    }
}

// ---------------- V transpose conversion: [b,s,kh,d] -> [b,kh,d,s] bf16 hi/lo ----------------
__global__ void vconv_kernel(){
    __shared__ float t[32][33];
    const int s0 = blockIdx.x*32;
    const int d0 = blockIdx.y*32;
    const int bkh = blockIdx.z;
    const int b  = bkh >> 3, kh = bkh & 7;
    #pragma unroll
    for (int i = 0; i < 4; ++i){
        const int s = s0 + threadIdx.y + i*8;
        const int d = d0 + threadIdx.x;
        t[threadIdx.y + i*8][threadIdx.x] =
            g_qkv[(size_t)(b*GS + s)*QKV_OUT + QKSTRIDE + kh*GHD + d];
    }
    __syncthreads();
    #pragma unroll
    for (int i = 0; i < 4; ++i){
        const int d = d0 + threadIdx.y + i*8;
        const int s = s0 + threadIdx.x;
        const float v = t[threadIdx.x][threadIdx.y + i*8];
        const __nv_bfloat16 h = __float2bfloat16(v);
        const __nv_bfloat16 l = __float2bfloat16(v - __bfloat162float(h));
        const size_t o = ((size_t)(bkh*GHD + d))*GS + s;
        g_vth[o] = h;
        g_vtl[o] = l;
    }
}

// ---------------- HMMA bf16x3 GEMM: 128x256 tile, 3-stage cp.async ----------------
#define GP    80
#define TBA   10240          // 128*80
#define TBB   20480          // 256*80
#define STG   (2*TBA + 2*TBB)     // 61440
#define NST   3
#define GEMM_SMEM (NST*STG)       // 184320

__device__ __forceinline__ void gemm_bf16x3_body(
    const __nv_bfloat16* __restrict__ Ah, const __nv_bfloat16* __restrict__ Al,
    const __nv_bfloat16* __restrict__ Bh, const __nv_bfloat16* __restrict__ Bl,
    float* __restrict__ C, int N, int K)
{
    extern __shared__ __align__(16) char dyn[];
    const uint32_t sb = smem_u32(dyn);

    const int tid  = threadIdx.x;
    const int wid  = tid >> 5;
    const int lane = tid & 31;
    const int wm   = (wid & 1) * 64;
    const int wn   = (wid >> 1) * 64;
    const int m0   = blockIdx.y * 128;
    const int n0   = blockIdx.x * 256;

    const __nv_bfloat16* Ahb = Ah + (size_t)m0*K;
    const __nv_bfloat16* Alb = Al + (size_t)m0*K;
    const __nv_bfloat16* Bhb = Bh + (size_t)n0*K;
    const __nv_bfloat16* Blb = Bl + (size_t)n0*K;

    auto issue = [&](int s, int k0){
        const uint32_t stg = sb + (uint32_t)(s*STG);
        // A tiles: 512 cp16 each (hi, lo)
        #pragma unroll
        for (int p = 0; p < 2; ++p){
            const int idx = p*256 + tid;
            const int row = idx >> 2;
            const int c16 = idx & 3;
            cp16(stg + (uint32_t)(row*GP + c16*16),       Ahb + (size_t)row*K + k0 + c16*8);
            cp16(stg + (uint32_t)(TBA + row*GP + c16*16), Alb + (size_t)row*K + k0 + c16*8);
        }
        // B tiles: 1024 cp16 each
        #pragma unroll
        for (int p = 0; p < 4; ++p){
            const int idx = p*256 + tid;
            const int row = idx >> 2;
            const int c16 = idx & 3;
            cp16(stg + (uint32_t)(2*TBA + row*GP + c16*16),       Bhb + (size_t)row*K + k0 + c16*8);
            cp16(stg + (uint32_t)(2*TBA + TBB + row*GP + c16*16), Blb + (size_t)row*K + k0 + c16*8);
        }
        cp_commit();
    };

    float acc[4][8][4];
    #pragma unroll
    for (int i=0;i<4;i++)
        #pragma unroll
        for (int j=0;j<8;j++)
            #pragma unroll
            for (int c=0;c<4;c++) acc[i][j][c] = 0.f;

    const int NIT = K / 32;
    issue(0, 0);
    issue(1, 32);

    const int arow = wm + (lane & 15);
    const int akb  = (lane >> 4) * 16;
    const int brow = wn + (lane & 7) + ((lane >> 4) << 3);
    const int bkb  = ((lane >> 3) & 1) * 16;

    for (int it = 0; it < NIT; ++it){
        if (it + 1 < NIT) cp_wait<1>(); else cp_wait<0>();
        __syncthreads();
        if (it + 2 < NIT) issue((it+2) % NST, (it+2)*32);

        const uint32_t stage = sb + (uint32_t)((it % NST) * STG);
        #pragma unroll
        for (int ks = 0; ks < 2; ++ks){
            uint32_t ah[4][4], al[4][4], bh[4][4], bl[4][4];
            #pragma unroll
            for (int mi = 0; mi < 4; ++mi){
                const uint32_t ad = stage + (uint32_t)((arow + mi*16)*GP + ks*32 + akb);
                ldmx4(ah[mi], ad);
                ldmx4(al[mi], ad + TBA);
            }
            #pragma unroll
            for (int n4 = 0; n4 < 4; ++n4){
                const uint32_t bd = stage + (uint32_t)(2*TBA + (brow + n4*16)*GP + ks*32 + bkb);
                ldmx4(bh[n4], bd);
                ldmx4(bl[n4], bd + TBB);
            }
            #pragma unroll
            for (int mi = 0; mi < 4; ++mi)
                #pragma unroll
                for (int ni = 0; ni < 8; ++ni){
                    const uint32_t* bhp = &bh[ni>>1][(ni&1)*2];
                    const uint32_t* blp = &bl[ni>>1][(ni&1)*2];
                    mma16816(acc[mi][ni], ah[mi], bhp);
                    mma16816(acc[mi][ni], ah[mi], blp);
                    mma16816(acc[mi][ni], al[mi], bhp);
                }
        }
        __syncthreads();
    }

    const int erow = (lane >> 2);
    const int ecol = (lane & 3) * 2;
    #pragma unroll
    for (int mi = 0; mi < 4; ++mi){
        #pragma unroll
        for (int ni = 0; ni < 8; ++ni){
            const int gm = m0 + wm + mi*16 + erow;
            const int gn = n0 + wn + ni*8 + ecol;
            *(float2*)(C + (size_t)gm*N + gn)     = make_float2(acc[mi][ni][0], acc[mi][ni][1]);
            *(float2*)(C + (size_t)(gm+8)*N + gn) = make_float2(acc[mi][ni][2], acc[mi][ni][3]);
        }
    }
}

__global__ __launch_bounds__(256, 1) void gemm_qkv_kernel(){
    gemm_bf16x3_body(g_xh, g_xl, g_wqkvh, g_wqkvl, g_qkv, QKV_OUT, GD);
}
__global__ __launch_bounds__(256, 1) void gemm_out_kernel(float* __restrict__ out){
    gemm_bf16x3_body(g_attnh, g_attnl, g_woh, g_wol, out, GD, GD);
}

// ---------------- HMMA flash attention (bf16x3, causal, GQA 4:1) ----------------
#define PQ 272
#define PK 272
#define PV 144
#define SQ_BYTES (128*PQ)
#define SK_BYTES (64*PK)
#define SV_BYTES (128*PV)
#define KV_STAGE (2*SK_BYTES + 2*SV_BYTES)
#define ATT_SMEM (2*SQ_BYTES + 2*KV_STAGE)

__global__ __launch_bounds__(256, 1) void attn_mma_kernel(){
    extern __shared__ __align__(16) char smraw[];
    const uint32_t sb = smem_u32(smraw);
    const int tid  = threadIdx.x;
    const int w    = tid >> 5;
    const int lane = tid & 31;
    const int qt = blockIdx.x, h = blockIdx.y, b = blockIdx.z;
    const int kh = h >> 2;

    const __nv_bfloat16* qhB = g_qkh + (size_t)(b*GS)*QKSTRIDE + h*GHD;
    const __nv_bfloat16* qlB = g_qkl + (size_t)(b*GS)*QKSTRIDE + h*GHD;
    const __nv_bfloat16* khB = g_qkh + (size_t)(b*GS)*QKSTRIDE + GD + kh*GHD;
    const __nv_bfloat16* klB = g_qkl + (size_t)(b*GS)*QKSTRIDE + GD + kh*GHD;
    const __nv_bfloat16* vhB = g_vth + (size_t)((b*GKH + kh)*GHD)*GS;
    const __nv_bfloat16* vlB = g_vtl + (size_t)((b*GKH + kh)*GHD)*GS;

    #pragma unroll
    for (int p = 0; p < 16; ++p){
        const int idx  = p*256 + tid;
        const int part = idx >> 11;
        const int rem  = idx & 2047;
        const int row  = rem >> 4;
        const int ch   = rem & 15;
        const __nv_bfloat16* src = (part ? qlB : qhB) + (size_t)(qt*128 + row)*QKSTRIDE + ch*8;
        cp16(sb + (uint32_t)(part*SQ_BYTES + row*PQ + ch*16), src);
    }
    cp_commit();

    auto issue_kv = [&](int kt){
        const uint32_t stg = sb + 2*SQ_BYTES + (uint32_t)((kt & 1) * KV_STAGE);
        #pragma unroll
        for (int p = 0; p < 16; ++p){
            const int idx = p*256 + tid;
            if (idx < 2048){
                const int part = idx >> 10;
                const int rem  = idx & 1023;
                const int row  = rem >> 4;
                const int ch   = rem & 15;
                const __nv_bfloat16* src = (part ? klB : khB) + (size_t)(kt*64 + row)*QKSTRIDE + ch*8;
                cp16(stg + (uint32_t)(part*SK_BYTES + row*PK + ch*16), src);
            } else {
                const int j    = idx - 2048;
                const int part = j >> 10;
                const int rem  = j & 1023;
                const int row  = rem >> 3;
                const int ch   = rem & 7;
                const __nv_bfloat16* src = (part ? vlB : vhB) + (size_t)row*GS + kt*64 + ch*8;
                cp16(stg + (uint32_t)(2*SK_BYTES + part*SV_BYTES + row*PV + ch*16), src);
            }
        }
        cp_commit();
    };

    issue_kv(0);

    const int arow = w*16 + (lane & 15);
    const int akb  = (lane >> 4) * 16;
    const int brow = (lane & 7) + ((lane >> 4) << 3);
    const int bkb  = ((lane >> 3) & 1) * 16;

    float oacc[16][4];
    #pragma unroll
    for (int i = 0; i < 16; ++i)
        #pragma unroll
        for (int c = 0; c < 4; ++c) oacc[i][c] = 0.f;
    float mr0 = -1e30f, mr1 = -1e30f, lr0 = 0.f, lr1 = 0.f;

    const int mx = 2*qt + 1;
    for (int kt = 0; kt <= mx; ++kt){
        cp_wait<0>();
        __syncthreads();
        if (kt < mx) issue_kv(kt+1);
        const uint32_t stg = sb + 2*SQ_BYTES + (uint32_t)((kt & 1) * KV_STAGE);

        float sacc[8][4];
        #pragma unroll
        for (int nf = 0; nf < 8; ++nf)
            #pragma unroll
            for (int c = 0; c < 4; ++c) sacc[nf][c] = 0.f;

        #pragma unroll
        for (int ks = 0; ks < 8; ++ks){
            uint32_t qh_t[4], ql_t[4];
            const uint32_t qa = sb + (uint32_t)(arow*PQ + ks*32 + akb);
            ldmx4(qh_t, qa);
            ldmx4(ql_t, qa + SQ_BYTES);
            uint32_t kfh[4][4], kfl[4][4];
            #pragma unroll
            for (int n4 = 0; n4 < 4; ++n4){
                const uint32_t ka = stg + (uint32_t)((brow + n4*16)*PK + ks*32 + bkb);
                ldmx4(kfh[n4], ka);
                ldmx4(kfl[n4], ka + SK_BYTES);
            }
            #pragma unroll
            for (int nf = 0; nf < 8; ++nf){
                const uint32_t* bh = &kfh[nf>>1][(nf&1)*2];
                const uint32_t* bl = &kfl[nf>>1][(nf&1)*2];
                mma16816(sacc[nf], qh_t, bh);
                mma16816(sacc[nf], qh_t, bl);
                mma16816(sacc[nf], ql_t, bh);
            }
        }

        if (kt >= 2*qt){
            const int r0 = qt*128 + w*16 + (lane >> 2);
            const int cb = kt*64 + (lane & 3)*2;
            #pragma unroll
            for (int nf = 0; nf < 8; ++nf){
                const int c = cb + nf*8;
                if (c     > r0)     sacc[nf][0] = -1e30f;
                if (c + 1 > r0)     sacc[nf][1] = -1e30f;
                if (c     > r0 + 8) sacc[nf][2] = -1e30f;
                if (c + 1 > r0 + 8) sacc[nf][3] = -1e30f;
            }
        }

        float rm0 = -1e30f, rm1 = -1e30f;
        #pragma unroll
        for (int nf = 0; nf < 8; ++nf){
            rm0 = fmaxf(rm0, fmaxf(sacc[nf][0], sacc[nf][1]));
            rm1 = fmaxf(rm1, fmaxf(sacc[nf][2], sacc[nf][3]));
        }
        rm0 = fmaxf(rm0, __shfl_xor_sync(0xffffffffu, rm0, 1));
        rm0 = fmaxf(rm0, __shfl_xor_sync(0xffffffffu, rm0, 2));
        rm1 = fmaxf(rm1, __shfl_xor_sync(0xffffffffu, rm1, 1));
        rm1 = fmaxf(rm1, __shfl_xor_sync(0xffffffffu, rm1, 2));
        const float mn0 = fmaxf(mr0, rm0);
        const float mn1 = fmaxf(mr1, rm1);
        const float a0 = __expf(mr0 - mn0);
        const float a1 = __expf(mr1 - mn1);
        float ps0 = 0.f, ps1 = 0.f;
        #pragma unroll
        for (int nf = 0; nf < 8; ++nf){
            sacc[nf][0] = __expf(sacc[nf][0] - mn0); ps0 += sacc[nf][0];
            sacc[nf][1] = __expf(sacc[nf][1] - mn0); ps0 += sacc[nf][1];
            sacc[nf][2] = __expf(sacc[nf][2] - mn1); ps1 += sacc[nf][2];
            sacc[nf][3] = __expf(sacc[nf][3] - mn1); ps1 += sacc[nf][3];
        }
        ps0 += __shfl_xor_sync(0xffffffffu, ps0, 1);
        ps0 += __shfl_xor_sync(0xffffffffu, ps0, 2);
        ps1 += __shfl_xor_sync(0xffffffffu, ps1, 1);
        ps1 += __shfl_xor_sync(0xffffffffu, ps1, 2);
        lr0 = lr0*a0 + ps0;  mr0 = mn0;
        lr1 = lr1*a1 + ps1;  mr1 = mn1;
        #pragma unroll
        for (int nf = 0; nf < 16; ++nf){
            oacc[nf][0] *= a0; oacc[nf][1] *= a0;
            oacc[nf][2] *= a1; oacc[nf][3] *= a1;
        }

        #pragma unroll
        for (int ks = 0; ks < 4; ++ks){
            uint32_t pah[4], pal[4];
            packhl(sacc[2*ks][0],   sacc[2*ks][1],   pah[0], pal[0]);
            packhl(sacc[2*ks][2],   sacc[2*ks][3],   pah[1], pal[1]);
            packhl(sacc[2*ks+1][0], sacc[2*ks+1][1], pah[2], pal[2]);
            packhl(sacc[2*ks+1][2], sacc[2*ks+1][3], pah[3], pal[3]);
            #pragma unroll
            for (int nd2 = 0; nd2 < 8; ++nd2){
                uint32_t vfh[4], vfl[4];
                const uint32_t va = stg + (uint32_t)(2*SK_BYTES + (brow + nd2*16)*PV + ks*32 + bkb);
                ldmx4(vfh, va);
                ldmx4(vfl, va + SV_BYTES);
                mma16816(oacc[nd2*2],   pah, &vfh[0]);
                mma16816(oacc[nd2*2],   pah, &vfl[0]);
                mma16816(oacc[nd2*2],   pal, &vfh[0]);
                mma16816(oacc[nd2*2+1], pah, &vfh[2]);
                mma16816(oacc[nd2*2+1], pah, &vfl[2]);
                mma16816(oacc[nd2*2+1], pal, &vfh[2]);
            }
        }
    }

    const float i0 = 1.f / lr0;
    const float i1 = 1.f / lr1;
    const int gr0 = b*GS + qt*128 + w*16 + (lane >> 2);
    const int cb  = h*GHD + (lane & 3)*2;
    #pragma unroll
    for (int nf = 0; nf < 16; ++nf){
        const float v0 = oacc[nf][0]*i0, v1 = oacc[nf][1]*i0;
        const float v2 = oacc[nf][2]*i1, v3 = oacc[nf][3]*i1;
        uint32_t h01, l01, h23, l23;
        packhl(v0, v1, h01, l01);
        packhl(v2, v3, h23, l23);
        const size_t o0 = (size_t)gr0*GD + cb + nf*8;
        const size_t o1 = (size_t)(gr0+8)*GD + cb + nf*8;
        *(uint32_t*)(g_attnh + o0) = h01;
        *(uint32_t*)(g_attnl + o0) = l01;
        *(uint32_t*)(g_attnh + o1) = h23;
        *(uint32_t*)(g_attnl + o1) = l23;
    }
}

// ---------------- launch ----------------
extern "C" void kernel_launch(void* const* d_in, const int* in_sizes, int n_in,
                              void* d_out, int out_size)
{
    const float* x    = (const float*)d_in[0];
    const float* Wqkv = (const float*)d_in[1];
    const float* Wo   = (const float*)d_in[2];
    float* out = (float*)d_out;

    cudaFuncSetAttribute(gemm_qkv_kernel, cudaFuncAttributeMaxDynamicSharedMemorySize, GEMM_SMEM);
    cudaFuncSetAttribute(gemm_out_kernel, cudaFuncAttributeMaxDynamicSharedMemorySize, GEMM_SMEM);
    cudaFuncSetAttribute(attn_mma_kernel, cudaFuncAttributeMaxDynamicSharedMemorySize, ATT_SMEM);

    unsigned long long *xh, *xl, *wqh, *wql, *woh, *wol;
    cudaGetSymbolAddress((void**)&xh,  g_xh);
    cudaGetSymbolAddress((void**)&xl,  g_xl);
    cudaGetSymbolAddress((void**)&wqh, g_wqkvh);
    cudaGetSymbolAddress((void**)&wql, g_wqkvl);
    cudaGetSymbolAddress((void**)&woh, g_woh);
    cudaGetSymbolAddress((void**)&wol, g_wol);

    const int nx  = GB*GS*GD/4;
    const int nwq = QKV_OUT*GD/4;
    const int nwo = GD*GD/4;
    cvt_pair_kernel<<<(nx +255)/256, 256>>>((const float4*)x,    xh,  xl,  nx);
    cvt_pair_kernel<<<(nwq+255)/256, 256>>>((const float4*)Wqkv, wqh, wql, nwq);
    cvt_pair_kernel<<<(nwo+255)/256, 256>>>((const float4*)Wo,   woh, wol, nwo);
    cs_kernel<<<(GS*64)/256, 256>>>();

    dim3 g1(QKV_OUT/256, (GB*GS)/128);
    gemm_qkv_kernel<<<g1, 256, GEMM_SMEM>>>();

    rope_fused_kernel<<<GB*GS, 256>>>();

    dim3 gv(GS/32, GHD/32, GB*GKH);
    vconv_kernel<<<gv, dim3(32,8)>>>();

    dim3 ga(GS/128, GH, GB);
    attn_mma_kernel<<<ga, 256, ATT_SMEM>>>();

    dim3 g2(GD/256, (GB*GS)/128);
    gemm_out_kernel<<<g2, 256, GEMM_SMEM>>>(out);
}

// round 14
// speedup vs baseline: 1.0006x; 1.0005x over previous
#include <cuda_runtime.h>
#include <cuda_bf16.h>
#include <math.h>
#include <stdint.h>

// ---------------- problem constants ----------------
#define GB   2
#define GS   2048
#define GD   4096
#define GH   32
#define GKH  8
#define GHD  128
#define QKV_OUT 6144
#define QKSTRIDE 5120     // q(4096) + k(1024) packed

// ---------------- device scratch ----------------
__device__ float g_qkv[GB*GS*QKV_OUT];                       // fp32 qkv (gemm out)
__device__ float2 g_cs[GS*64];                               // rope cos/sin table
__device__ __nv_bfloat16 g_xh[GB*GS*GD],      g_xl[GB*GS*GD];
__device__ __nv_bfloat16 g_wqkvh[QKV_OUT*GD], g_wqkvl[QKV_OUT*GD];
__device__ __nv_bfloat16 g_woh[GD*GD],        g_wol[GD*GD];
__device__ __nv_bfloat16 g_attnh[GB*GS*GD],   g_attnl[GB*GS*GD];
__device__ __nv_bfloat16 g_qkh[GB*GS*QKSTRIDE], g_qkl[GB*GS*QKSTRIDE];   // roped q(scaled)+k, bf16 hi/lo
__device__ __nv_bfloat16 g_vth[GB*GKH*GHD*GS],  g_vtl[GB*GKH*GHD*GS];    // V transposed [b,kh,d,s]

// ---------------- smem addr helper ----------------
__device__ __forceinline__ uint32_t smem_u32(const void* p){
    uint32_t a;
    asm("{ .reg .u64 t; cvta.to.shared.u64 t, %1; cvt.u32.u64 %0, t; }" : "=r"(a) : "l"(p));
    return a;
}

// ---------------- HMMA / cp.async helpers ----------------
__device__ __forceinline__ void ldmx4(uint32_t* r, uint32_t addr){
    asm volatile("ldmatrix.sync.aligned.m8n8.x4.shared.b16 {%0,%1,%2,%3}, [%4];"
        : "=r"(r[0]), "=r"(r[1]), "=r"(r[2]), "=r"(r[3]) : "r"(addr));
}
__device__ __forceinline__ void mma16816(float* c, const uint32_t* a, const uint32_t* b){
    asm volatile(
        "mma.sync.aligned.m16n8k16.row.col.f32.bf16.bf16.f32 "
        "{%0,%1,%2,%3}, {%4,%5,%6,%7}, {%8,%9}, {%0,%1,%2,%3};"
        : "+f"(c[0]), "+f"(c[1]), "+f"(c[2]), "+f"(c[3])
        : "r"(a[0]), "r"(a[1]), "r"(a[2]), "r"(a[3]), "r"(b[0]), "r"(b[1]));
}
__device__ __forceinline__ void cp16(uint32_t saddr, const void* g){
    asm volatile("cp.async.cg.shared.global [%0], [%1], 16;"
        :: "r"(saddr), "l"(__cvta_generic_to_global(g)) : "memory");
}
__device__ __forceinline__ void cp_commit(){
    asm volatile("cp.async.commit_group;" ::: "memory");
}
template <int N>
__device__ __forceinline__ void cp_wait(){
    asm volatile("cp.async.wait_group %0;" :: "n"(N) : "memory");
}

// ---------------- bf16 hi/lo helpers ----------------
__device__ __forceinline__ void hilo4(float4 v, unsigned long long& h, unsigned long long& l){
    __nv_bfloat16 h0 = __float2bfloat16(v.x);
    __nv_bfloat16 h1 = __float2bfloat16(v.y);
    __nv_bfloat16 h2 = __float2bfloat16(v.z);
    __nv_bfloat16 h3 = __float2bfloat16(v.w);
    __nv_bfloat16 l0 = __float2bfloat16(v.x - __bfloat162float(h0));
    __nv_bfloat16 l1 = __float2bfloat16(v.y - __bfloat162float(h1));
    __nv_bfloat16 l2 = __float2bfloat16(v.z - __bfloat162float(h2));
    __nv_bfloat16 l3 = __float2bfloat16(v.w - __bfloat162float(h3));
    h = (unsigned long long)__bfloat16_as_ushort(h0)
      | ((unsigned long long)__bfloat16_as_ushort(h1) << 16)
      | ((unsigned long long)__bfloat16_as_ushort(h2) << 32)
      | ((unsigned long long)__bfloat16_as_ushort(h3) << 48);
    l = (unsigned long long)__bfloat16_as_ushort(l0)
      | ((unsigned long long)__bfloat16_as_ushort(l1) << 16)
      | ((unsigned long long)__bfloat16_as_ushort(l2) << 32)
      | ((unsigned long long)__bfloat16_as_ushort(l3) << 48);
}
__device__ __forceinline__ void packhl(float f0, float f1, uint32_t& h, uint32_t& l){
    __nv_bfloat16 h0 = __float2bfloat16(f0);
    __nv_bfloat16 h1 = __float2bfloat16(f1);
    __nv_bfloat16 b0 = __float2bfloat16(f0 - __bfloat162float(h0));
    __nv_bfloat16 b1 = __float2bfloat16(f1 - __bfloat162float(h1));
    h = (uint32_t)__bfloat16_as_ushort(h0) | ((uint32_t)__bfloat16_as_ushort(h1) << 16);
    l = (uint32_t)__bfloat16_as_ushort(b0) | ((uint32_t)__bfloat16_as_ushort(b1) << 16);
}

// ---------------- fp32 -> bf16 hi/lo ----------------
__global__ __launch_bounds__(256) void cvt_pair_kernel(const float4* __restrict__ src,
                                                       unsigned long long* __restrict__ h,
                                                       unsigned long long* __restrict__ l,
                                                       int n4){
    const int i = blockIdx.x*blockDim.x + threadIdx.x;
    if (i < n4){
        unsigned long long hh, ll;
        hilo4(src[i], hh, ll);
        h[i] = hh;
        l[i] = ll;
    }
}

// ---------------- rope cos/sin table ----------------
__global__ __launch_bounds__(256) void cs_kernel(){
    const int idx = blockIdx.x*256 + threadIdx.x;   // GS*64
    const int pos = idx >> 6;
    const int i   = idx & 63;
    const float inv = powf(500000.0f, -(float)i * (1.0f/64.0f));
    float sn, cs;
    sincosf((float)pos * inv, &sn, &cs);
    g_cs[idx] = make_float2(cs, sn);
}

// ---------------- fused RoPE + bf16 hi/lo q/k conversion ----------------
// reads fp32 g_qkv, writes g_qkh/g_qkl (stride 5120). scale folded into q.
__global__ __launch_bounds__(256) void rope_fused_kernel(){
    const int row = blockIdx.x;                  // b*S + s
    const int pos = row & (GS-1);
    const float SCL = 0.08838834764831845f;
    const float* src = g_qkv + (size_t)row * QKV_OUT;
    __nv_bfloat16* dh = g_qkh + (size_t)row * QKSTRIDE;
    __nv_bfloat16* dl = g_qkl + (size_t)row * QKSTRIDE;

    for (int it = threadIdx.x; it < 40*16; it += 256){
        const int hh = it >> 4;
        const int qi = (it & 15) * 4;
        const int off = (hh < GH) ? hh*GHD : GH*GHD + (hh-GH)*GHD;
        const float4 x1 = *(const float4*)(src + off + qi);
        const float4 x2 = *(const float4*)(src + off + qi + 64);
        const float2 c0 = g_cs[pos*64 + qi];
        const float2 c1 = g_cs[pos*64 + qi + 1];
        const float2 c2 = g_cs[pos*64 + qi + 2];
        const float2 c3 = g_cs[pos*64 + qi + 3];
        float4 r1 = make_float4(x1.x*c0.x - x2.x*c0.y, x1.y*c1.x - x2.y*c1.y,
                                x1.z*c2.x - x2.z*c2.y, x1.w*c3.x - x2.w*c3.y);
        float4 r2 = make_float4(x2.x*c0.x + x1.x*c0.y, x2.y*c1.x + x1.y*c1.y,
                                x2.z*c2.x + x1.z*c2.y, x2.w*c3.x + x1.w*c3.y);
        if (hh < GH){
            r1.x*=SCL; r1.y*=SCL; r1.z*=SCL; r1.w*=SCL;
            r2.x*=SCL; r2.y*=SCL; r2.z*=SCL; r2.w*=SCL;
        }
        unsigned long long h1, l1, h2, l2;
        hilo4(r1, h1, l1);
        hilo4(r2, h2, l2);
        *(unsigned long long*)(dh + off + qi)      = h1;
        *(unsigned long long*)(dl + off + qi)      = l1;
        *(unsigned long long*)(dh + off + qi + 64) = h2;
        *(unsigned long long*)(dl + off + qi + 64) = l2;
    }
}

// ---------------- V transpose conversion: [b,s,kh,d] -> [b,kh,d,s] bf16 hi/lo ----------------
__global__ void vconv_kernel(){
    __shared__ float t[32][33];
    const int s0 = blockIdx.x*32;
    const int d0 = blockIdx.y*32;
    const int bkh = blockIdx.z;
    const int b  = bkh >> 3, kh = bkh & 7;
    #pragma unroll
    for (int i = 0; i < 4; ++i){
        const int s = s0 + threadIdx.y + i*8;
        const int d = d0 + threadIdx.x;
        t[threadIdx.y + i*8][threadIdx.x] =
            g_qkv[(size_t)(b*GS + s)*QKV_OUT + QKSTRIDE + kh*GHD + d];
    }
    __syncthreads();
    #pragma unroll
    for (int i = 0; i < 4; ++i){
        const int d = d0 + threadIdx.y + i*8;
        const int s = s0 + threadIdx.x;
        const float v = t[threadIdx.x][threadIdx.y + i*8];
        const __nv_bfloat16 h = __float2bfloat16(v);
        const __nv_bfloat16 l = __float2bfloat16(v - __bfloat162float(h));
        const size_t o = ((size_t)(bkh*GHD + d))*GS + s;
        g_vth[o] = h;
        g_vtl[o] = l;
    }
}

// ---------------- HMMA bf16x3 GEMM: 128x256 tile, 3-stage cp.async ----------------
#define GP    80
#define TBA   10240          // 128*80
#define TBB   20480          // 256*80
#define STG   (2*TBA + 2*TBB)     // 61440
#define NST   3
#define GEMM_SMEM (NST*STG)       // 184320

__device__ __forceinline__ void gemm_bf16x3_body(
    const __nv_bfloat16* __restrict__ Ah, const __nv_bfloat16* __restrict__ Al,
    const __nv_bfloat16* __restrict__ Bh, const __nv_bfloat16* __restrict__ Bl,
    float* __restrict__ C, int N, int K)
{
    extern __shared__ __align__(16) char dyn[];
    const uint32_t sb = smem_u32(dyn);

    const int tid  = threadIdx.x;
    const int wid  = tid >> 5;
    const int lane = tid & 31;
    const int wm   = (wid & 1) * 64;
    const int wn   = (wid >> 1) * 64;
    const int m0   = blockIdx.y * 128;
    const int n0   = blockIdx.x * 256;

    const __nv_bfloat16* Ahb = Ah + (size_t)m0*K;
    const __nv_bfloat16* Alb = Al + (size_t)m0*K;
    const __nv_bfloat16* Bhb = Bh + (size_t)n0*K;
    const __nv_bfloat16* Blb = Bl + (size_t)n0*K;

    auto issue = [&](int s, int k0){
        const uint32_t stg = sb + (uint32_t)(s*STG);
        // A tiles: 512 cp16 each (hi, lo)
        #pragma unroll
        for (int p = 0; p < 2; ++p){
            const int idx = p*256 + tid;
            const int row = idx >> 2;
            const int c16 = idx & 3;
            cp16(stg + (uint32_t)(row*GP + c16*16),       Ahb + (size_t)row*K + k0 + c16*8);
            cp16(stg + (uint32_t)(TBA + row*GP + c16*16), Alb + (size_t)row*K + k0 + c16*8);
        }
        // B tiles: 1024 cp16 each
        #pragma unroll
        for (int p = 0; p < 4; ++p){
            const int idx = p*256 + tid;
            const int row = idx >> 2;
            const int c16 = idx & 3;
            cp16(stg + (uint32_t)(2*TBA + row*GP + c16*16),       Bhb + (size_t)row*K + k0 + c16*8);
            cp16(stg + (uint32_t)(2*TBA + TBB + row*GP + c16*16), Blb + (size_t)row*K + k0 + c16*8);
        }
        cp_commit();
    };

    float acc[4][8][4];
    #pragma unroll
    for (int i=0;i<4;i++)
        #pragma unroll
        for (int j=0;j<8;j++)
            #pragma unroll
            for (int c=0;c<4;c++) acc[i][j][c] = 0.f;

    const int NIT = K / 32;
    issue(0, 0);
    issue(1, 32);

    const int arow = wm + (lane & 15);
    const int akb  = (lane >> 4) * 16;
    const int brow = wn + (lane & 7) + ((lane >> 4) << 3);
    const int bkb  = ((lane >> 3) & 1) * 16;

    for (int it = 0; it < NIT; ++it){
        if (it + 1 < NIT) cp_wait<1>(); else cp_wait<0>();
        __syncthreads();
        if (it + 2 < NIT) issue((it+2) % NST, (it+2)*32);

        const uint32_t stage = sb + (uint32_t)((it % NST) * STG);
        #pragma unroll
        for (int ks = 0; ks < 2; ++ks){
            uint32_t ah[4][4], al[4][4], bh[4][4], bl[4][4];
            #pragma unroll
            for (int mi = 0; mi < 4; ++mi){
                const uint32_t ad = stage + (uint32_t)((arow + mi*16)*GP + ks*32 + akb);
                ldmx4(ah[mi], ad);
                ldmx4(al[mi], ad + TBA);
            }
            #pragma unroll
            for (int n4 = 0; n4 < 4; ++n4){
                const uint32_t bd = stage + (uint32_t)(2*TBA + (brow + n4*16)*GP + ks*32 + bkb);
                ldmx4(bh[n4], bd);
                ldmx4(bl[n4], bd + TBB);
            }
            #pragma unroll
            for (int mi = 0; mi < 4; ++mi)
                #pragma unroll
                for (int ni = 0; ni < 8; ++ni){
                    const uint32_t* bhp = &bh[ni>>1][(ni&1)*2];
                    const uint32_t* blp = &bl[ni>>1][(ni&1)*2];
                    mma16816(acc[mi][ni], ah[mi], bhp);
                    mma16816(acc[mi][ni], ah[mi], blp);
                    mma16816(acc[mi][ni], al[mi], bhp);
                }
        }
        __syncthreads();
    }

    const int erow = (lane >> 2);
    const int ecol = (lane & 3) * 2;
    #pragma unroll
    for (int mi = 0; mi < 4; ++mi){
        #pragma unroll
        for (int ni = 0; ni < 8; ++ni){
            const int gm = m0 + wm + mi*16 + erow;
            const int gn = n0 + wn + ni*8 + ecol;
            *(float2*)(C + (size_t)gm*N + gn)     = make_float2(acc[mi][ni][0], acc[mi][ni][1]);
            *(float2*)(C + (size_t)(gm+8)*N + gn) = make_float2(acc[mi][ni][2], acc[mi][ni][3]);
        }
    }
}

__global__ __launch_bounds__(256, 1) void gemm_qkv_kernel(){
    gemm_bf16x3_body(g_xh, g_xl, g_wqkvh, g_wqkvl, g_qkv, QKV_OUT, GD);
}
__global__ __launch_bounds__(256, 1) void gemm_out_kernel(float* __restrict__ out){
    gemm_bf16x3_body(g_attnh, g_attnl, g_woh, g_wol, out, GD, GD);
}

// ---------------- HMMA flash attention (bf16x3, causal, GQA 4:1) ----------------
#define PQ 272
#define PK 272
#define PV 144
#define SQ_BYTES (128*PQ)
#define SK_BYTES (64*PK)
#define SV_BYTES (128*PV)
#define KV_STAGE (2*SK_BYTES + 2*SV_BYTES)
#define ATT_SMEM (2*SQ_BYTES + 2*KV_STAGE)

__global__ __launch_bounds__(256, 1) void attn_mma_kernel(){
    extern __shared__ __align__(16) char smraw[];
    const uint32_t sb = smem_u32(smraw);
    const int tid  = threadIdx.x;
    const int w    = tid >> 5;
    const int lane = tid & 31;
    const int qt = blockIdx.x, h = blockIdx.y, b = blockIdx.z;
    const int kh = h >> 2;

    const __nv_bfloat16* qhB = g_qkh + (size_t)(b*GS)*QKSTRIDE + h*GHD;
    const __nv_bfloat16* qlB = g_qkl + (size_t)(b*GS)*QKSTRIDE + h*GHD;
    const __nv_bfloat16* khB = g_qkh + (size_t)(b*GS)*QKSTRIDE + GD + kh*GHD;
    const __nv_bfloat16* klB = g_qkl + (size_t)(b*GS)*QKSTRIDE + GD + kh*GHD;
    const __nv_bfloat16* vhB = g_vth + (size_t)((b*GKH + kh)*GHD)*GS;
    const __nv_bfloat16* vlB = g_vtl + (size_t)((b*GKH + kh)*GHD)*GS;

    #pragma unroll
    for (int p = 0; p < 16; ++p){
        const int idx  = p*256 + tid;
        const int part = idx >> 11;
        const int rem  = idx & 2047;
        const int row  = rem >> 4;
        const int ch   = rem & 15;
        const __nv_bfloat16* src = (part ? qlB : qhB) + (size_t)(qt*128 + row)*QKSTRIDE + ch*8;
        cp16(sb + (uint32_t)(part*SQ_BYTES + row*PQ + ch*16), src);
    }
    cp_commit();

    auto issue_kv = [&](int kt){
        const uint32_t stg = sb + 2*SQ_BYTES + (uint32_t)((kt & 1) * KV_STAGE);
        #pragma unroll
        for (int p = 0; p < 16; ++p){
            const int idx = p*256 + tid;
            if (idx < 2048){
                const int part = idx >> 10;
                const int rem  = idx & 1023;
                const int row  = rem >> 4;
                const int ch   = rem & 15;
                const __nv_bfloat16* src = (part ? klB : khB) + (size_t)(kt*64 + row)*QKSTRIDE + ch*8;
                cp16(stg + (uint32_t)(part*SK_BYTES + row*PK + ch*16), src);
            } else {
                const int j    = idx - 2048;
                const int part = j >> 10;
                const int rem  = j & 1023;
                const int row  = rem >> 3;
                const int ch   = rem & 7;
                const __nv_bfloat16* src = (part ? vlB : vhB) + (size_t)row*GS + kt*64 + ch*8;
                cp16(stg + (uint32_t)(2*SK_BYTES + part*SV_BYTES + row*PV + ch*16), src);
            }
        }
        cp_commit();
    };

    issue_kv(0);

    const int arow = w*16 + (lane & 15);
    const int akb  = (lane >> 4) * 16;
    const int brow = (lane & 7) + ((lane >> 4) << 3);
    const int bkb  = ((lane >> 3) & 1) * 16;

    float oacc[16][4];
    #pragma unroll
    for (int i = 0; i < 16; ++i)
        #pragma unroll
        for (int c = 0; c < 4; ++c) oacc[i][c] = 0.f;
    float mr0 = -1e30f, mr1 = -1e30f, lr0 = 0.f, lr1 = 0.f;

    const int mx = 2*qt + 1;
    for (int kt = 0; kt <= mx; ++kt){
        cp_wait<0>();
        __syncthreads();
        if (kt < mx) issue_kv(kt+1);
        const uint32_t stg = sb + 2*SQ_BYTES + (uint32_t)((kt & 1) * KV_STAGE);

        float sacc[8][4];
        #pragma unroll
        for (int nf = 0; nf < 8; ++nf)
            #pragma unroll
            for (int c = 0; c < 4; ++c) sacc[nf][c] = 0.f;

        #pragma unroll
        for (int ks = 0; ks < 8; ++ks){
            uint32_t qh_t[4], ql_t[4];
            const uint32_t qa = sb + (uint32_t)(arow*PQ + ks*32 + akb);
            ldmx4(qh_t, qa);
            ldmx4(ql_t, qa + SQ_BYTES);
            uint32_t kfh[4][4], kfl[4][4];
            #pragma unroll
            for (int n4 = 0; n4 < 4; ++n4){
                const uint32_t ka = stg + (uint32_t)((brow + n4*16)*PK + ks*32 + bkb);
                ldmx4(kfh[n4], ka);
                ldmx4(kfl[n4], ka + SK_BYTES);
            }
            #pragma unroll
            for (int nf = 0; nf < 8; ++nf){
                const uint32_t* bh = &kfh[nf>>1][(nf&1)*2];
                const uint32_t* bl = &kfl[nf>>1][(nf&1)*2];
                mma16816(sacc[nf], qh_t, bh);
                mma16816(sacc[nf], qh_t, bl);
                mma16816(sacc[nf], ql_t, bh);
            }
        }

        if (kt >= 2*qt){
            const int r0 = qt*128 + w*16 + (lane >> 2);
            const int cb = kt*64 + (lane & 3)*2;
            #pragma unroll
            for (int nf = 0; nf < 8; ++nf){
                const int c = cb + nf*8;
                if (c     > r0)     sacc[nf][0] = -1e30f;
                if (c + 1 > r0)     sacc[nf][1] = -1e30f;
                if (c     > r0 + 8) sacc[nf][2] = -1e30f;
                if (c + 1 > r0 + 8) sacc[nf][3] = -1e30f;
            }
        }

        float rm0 = -1e30f, rm1 = -1e30f;
        #pragma unroll
        for (int nf = 0; nf < 8; ++nf){
            rm0 = fmaxf(rm0, fmaxf(sacc[nf][0], sacc[nf][1]));
            rm1 = fmaxf(rm1, fmaxf(sacc[nf][2], sacc[nf][3]));
        }
        rm0 = fmaxf(rm0, __shfl_xor_sync(0xffffffffu, rm0, 1));
        rm0 = fmaxf(rm0, __shfl_xor_sync(0xffffffffu, rm0, 2));
        rm1 = fmaxf(rm1, __shfl_xor_sync(0xffffffffu, rm1, 1));
        rm1 = fmaxf(rm1, __shfl_xor_sync(0xffffffffu, rm1, 2));
        const float mn0 = fmaxf(mr0, rm0);
        const float mn1 = fmaxf(mr1, rm1);
        const float a0 = __expf(mr0 - mn0);
        const float a1 = __expf(mr1 - mn1);
        float ps0 = 0.f, ps1 = 0.f;
        #pragma unroll
        for (int nf = 0; nf < 8; ++nf){
            sacc[nf][0] = __expf(sacc[nf][0] - mn0); ps0 += sacc[nf][0];
            sacc[nf][1] = __expf(sacc[nf][1] - mn0); ps0 += sacc[nf][1];
            sacc[nf][2] = __expf(sacc[nf][2] - mn1); ps1 += sacc[nf][2];
            sacc[nf][3] = __expf(sacc[nf][3] - mn1); ps1 += sacc[nf][3];
        }
        ps0 += __shfl_xor_sync(0xffffffffu, ps0, 1);
        ps0 += __shfl_xor_sync(0xffffffffu, ps0, 2);
        ps1 += __shfl_xor_sync(0xffffffffu, ps1, 1);
        ps1 += __shfl_xor_sync(0xffffffffu, ps1, 2);
        lr0 = lr0*a0 + ps0;  mr0 = mn0;
        lr1 = lr1*a1 + ps1;  mr1 = mn1;
        #pragma unroll
        for (int nf = 0; nf < 16; ++nf){
            oacc[nf][0] *= a0; oacc[nf][1] *= a0;
            oacc[nf][2] *= a1; oacc[nf][3] *= a1;
        }

        #pragma unroll
        for (int ks = 0; ks < 4; ++ks){
            uint32_t pah[4], pal[4];
            packhl(sacc[2*ks][0],   sacc[2*ks][1],   pah[0], pal[0]);
            packhl(sacc[2*ks][2],   sacc[2*ks][3],   pah[1], pal[1]);
            packhl(sacc[2*ks+1][0], sacc[2*ks+1][1], pah[2], pal[2]);
            packhl(sacc[2*ks+1][2], sacc[2*ks+1][3], pah[3], pal[3]);
            #pragma unroll
            for (int nd2 = 0; nd2 < 8; ++nd2){
                uint32_t vfh[4], vfl[4];
                const uint32_t va = stg + (uint32_t)(2*SK_BYTES + (brow + nd2*16)*PV + ks*32 + bkb);
                ldmx4(vfh, va);
                ldmx4(vfl, va + SV_BYTES);
                mma16816(oacc[nd2*2],   pah, &vfh[0]);
                mma16816(oacc[nd2*2],   pah, &vfl[0]);
                mma16816(oacc[nd2*2],   pal, &vfh[0]);
                mma16816(oacc[nd2*2+1], pah, &vfh[2]);
                mma16816(oacc[nd2*2+1], pah, &vfl[2]);
                mma16816(oacc[nd2*2+1], pal, &vfh[2]);
            }
        }
    }

    const float i0 = 1.f / lr0;
    const float i1 = 1.f / lr1;
    const int gr0 = b*GS + qt*128 + w*16 + (lane >> 2);
    const int cb  = h*GHD + (lane & 3)*2;
    #pragma unroll
    for (int nf = 0; nf < 16; ++nf){
        const float v0 = oacc[nf][0]*i0, v1 = oacc[nf][1]*i0;
        const float v2 = oacc[nf][2]*i1, v3 = oacc[nf][3]*i1;
        uint32_t h01, l01, h23, l23;
        packhl(v0, v1, h01, l01);
        packhl(v2, v3, h23, l23);
        const size_t o0 = (size_t)gr0*GD + cb + nf*8;
        const size_t o1 = (size_t)(gr0+8)*GD + cb + nf*8;
        *(uint32_t*)(g_attnh + o0) = h01;
        *(uint32_t*)(g_attnl + o0) = l01;
        *(uint32_t*)(g_attnh + o1) = h23;
        *(uint32_t*)(g_attnl + o1) = l23;
    }
}

// ---------------- launch ----------------
extern "C" void kernel_launch(void* const* d_in, const int* in_sizes, int n_in,
                              void* d_out, int out_size)
{
    const float* x    = (const float*)d_in[0];
    const float* Wqkv = (const float*)d_in[1];
    const float* Wo   = (const float*)d_in[2];
    float* out = (float*)d_out;

    cudaFuncSetAttribute(gemm_qkv_kernel, cudaFuncAttributeMaxDynamicSharedMemorySize, GEMM_SMEM);
    cudaFuncSetAttribute(gemm_out_kernel, cudaFuncAttributeMaxDynamicSharedMemorySize, GEMM_SMEM);
    cudaFuncSetAttribute(attn_mma_kernel, cudaFuncAttributeMaxDynamicSharedMemorySize, ATT_SMEM);

    unsigned long long *xh, *xl, *wqh, *wql, *woh, *wol;
    cudaGetSymbolAddress((void**)&xh,  g_xh);
    cudaGetSymbolAddress((void**)&xl,  g_xl);
    cudaGetSymbolAddress((void**)&wqh, g_wqkvh);
    cudaGetSymbolAddress((void**)&wql, g_wqkvl);
    cudaGetSymbolAddress((void**)&woh, g_woh);
    cudaGetSymbolAddress((void**)&wol, g_wol);

    const int nx  = GB*GS*GD/4;
    const int nwq = QKV_OUT*GD/4;
    const int nwo = GD*GD/4;
    cvt_pair_kernel<<<(nx +255)/256, 256>>>((const float4*)x,    xh,  xl,  nx);
    cvt_pair_kernel<<<(nwq+255)/256, 256>>>((const float4*)Wqkv, wqh, wql, nwq);
    cvt_pair_kernel<<<(nwo+255)/256, 256>>>((const float4*)Wo,   woh, wol, nwo);
    cs_kernel<<<(GS*64)/256, 256>>>();

    dim3 g1(QKV_OUT/256, (GB*GS)/128);
    gemm_qkv_kernel<<<g1, 256, GEMM_SMEM>>>();

    rope_fused_kernel<<<GB*GS, 256>>>();

    dim3 gv(GS/32, GHD/32, GB*GKH);
    vconv_kernel<<<gv, dim3(32,8)>>>();

    dim3 ga(GS/128, GH, GB);
    attn_mma_kernel<<<ga, 256, ATT_SMEM>>>();

    dim3 g2(GD/256, (GB*GS)/128);
    gemm_out_kernel<<<g2, 256, GEMM_SMEM>>>(out);
}